// round 1
// baseline (speedup 1.0000x reference)
#include <cuda_runtime.h>
#include <cuda_bf16.h>

#define B_   8
#define K_   128
#define S_   256
#define NP_  1024
#define QR_  16
#define PP   4
#define KC   32

__device__ __forceinline__ unsigned long long pack2(float lo, float hi) {
    unsigned long long r;
    asm("mov.b64 %0, {%1, %2};" : "=l"(r) : "f"(lo), "f"(hi));
    return r;
}
__device__ __forceinline__ void unpack2(unsigned long long v, float& lo, float& hi) {
    asm("mov.b64 {%0, %1}, %2;" : "=f"(lo), "=f"(hi) : "l"(v));
}
__device__ __forceinline__ void ffma2(unsigned long long& d,
                                      unsigned long long a,
                                      unsigned long long b) {
    asm("fma.rn.f32x2 %0, %1, %2, %0;" : "+l"(d) : "l"(a), "l"(b));
}

__global__ __launch_bounds__(256, 2)
void backproj_kernel(const float* __restrict__ y,
                     const float* __restrict__ W,
                     float* __restrict__ out) {
    const int n  = blockIdx.x;
    const int pg = blockIdx.y;
    const int t  = threadIdx.x;

    __shared__ float Ys[KC][S_];
    __shared__ float Ws[PP][KC][QR_];

    unsigned long long acc[PP][8];
    #pragma unroll
    for (int pp = 0; pp < PP; ++pp)
        #pragma unroll
        for (int j = 0; j < 8; ++j)
            acc[pp][j] = 0ULL;

    for (int k0 = 0; k0 < K_; k0 += KC) {
        const float4* ysrc = (const float4*)(y + (size_t)(n * K_ + k0) * S_);
        float4* ydst = (float4*)&Ys[0][0];
        #pragma unroll
        for (int i = 0; i < (KC * S_ / 4) / 256; ++i)
            ydst[t + i * 256] = ysrc[t + i * 256];

        #pragma unroll
        for (int i = t; i < PP * KC * QR_ / 4; i += 256) {
            int pp  = i >> 7;
            int rem = i & 127;
            int kk  = rem >> 2;
            int j4  = rem & 3;
            ((float4*)&Ws[pp][kk][0])[j4] =
                ((const float4*)(W + (size_t)(k0 + kk) * (NP_ * QR_)
                                   + (size_t)(pg * PP + pp) * QR_))[j4];
        }
        __syncthreads();

        #pragma unroll 8
        for (int kk = 0; kk < KC; ++kk) {
            float yv = Ys[kk][t];
            unsigned long long yy = pack2(yv, yv);
            #pragma unroll
            for (int pp = 0; pp < PP; ++pp) {
                const ulonglong2* wr = (const ulonglong2*)&Ws[pp][kk][0];
                ulonglong2 w01 = wr[0];   // floats 0..3  -> pairs 0,1
                ulonglong2 w23 = wr[1];   // floats 4..7  -> pairs 2,3
                ulonglong2 w45 = wr[2];   // floats 8..11 -> pairs 4,5
                ulonglong2 w67 = wr[3];   // floats 12..15-> pairs 6,7
                ffma2(acc[pp][0], yy, w01.x);
                ffma2(acc[pp][1], yy, w01.y);
                ffma2(acc[pp][2], yy, w23.x);
                ffma2(acc[pp][3], yy, w23.y);
                ffma2(acc[pp][4], yy, w45.x);
                ffma2(acc[pp][5], yy, w45.y);
                ffma2(acc[pp][6], yy, w67.x);
                ffma2(acc[pp][7], yy, w67.y);
            }
        }
        __syncthreads();
    }

    const int y_ = t >> 4;
    const int z  = t & 15;
    #pragma unroll
    for (int pp = 0; pp < PP; ++pp) {
        float* ob = out + (size_t)n * 4194304
                        + (size_t)(pg * PP + pp) * 4096
                        + y_ * 256 + z * 4;
        #pragma unroll
        for (int q = 0; q < 4; ++q) {
            float4 v;
            unpack2(acc[pp][2 * q],     v.x, v.y);
            unpack2(acc[pp][2 * q + 1], v.z, v.w);
            *(float4*)(ob + q * 64) = v;
        }
    }
}

extern "C" void kernel_launch(void* const* d_in, const int* in_sizes, int n_in,
                              void* d_out, int out_size) {
    const float* y = (const float*)d_in[0];
    const float* W = (const float*)d_in[1];
    float* out = (float*)d_out;
    dim3 grid(B_, NP_ / PP);
    backproj_kernel<<<grid, 256>>>(y, W, out);
}

// round 2
// speedup vs baseline: 1.2828x; 1.2828x over previous
#include <cuda_runtime.h>
#include <cuda_bf16.h>

#define B_   8
#define K_   128
#define S_   256
#define NP_  1024
#define QR_  16
#define KC   32
#define ST   4      // spatial per thread
#define PT   2      // p per thread
#define PG   8      // p per block  (PT * 4 thread-groups)

__device__ __forceinline__ unsigned long long pack2(float lo, float hi) {
    unsigned long long r;
    asm("mov.b64 %0, {%1, %2};" : "=l"(r) : "f"(lo), "f"(hi));
    return r;
}
__device__ __forceinline__ void unpack2(unsigned long long v, float& lo, float& hi) {
    asm("mov.b64 {%0, %1}, %2;" : "=f"(lo), "=f"(hi) : "l"(v));
}
__device__ __forceinline__ void ffma2(unsigned long long& d,
                                      unsigned long long a,
                                      unsigned long long b) {
    asm("fma.rn.f32x2 %0, %1, %2, %0;" : "+l"(d) : "l"(a), "l"(b));
}

__global__ __launch_bounds__(256, 1)
void backproj_kernel(const float* __restrict__ y,
                     const float* __restrict__ W,
                     float* __restrict__ out) {
    const int n  = blockIdx.x;     // 0..7
    const int pg = blockIdx.y;     // 0..127  -> p base = pg*PG
    const int t  = threadIdx.x;    // 0..255
    const int s  = t & 63;         // spatial base; handles s, s+64, s+128, s+192
    const int g  = t >> 6;         // p-pair group 0..3

    __shared__ float Ys[KC][64][ST];     // transposed: [kk][s][si], 32 KB
    __shared__ float Ws[KC][PG][QR_];    // 16 KB

    // acc[si][pp][j]  : j packs qr = 2j, 2j+1
    unsigned long long acc[ST][PT][8];
    #pragma unroll
    for (int si = 0; si < ST; ++si)
        #pragma unroll
        for (int pp = 0; pp < PT; ++pp)
            #pragma unroll
            for (int j = 0; j < 8; ++j)
                acc[si][pp][j] = 0ULL;

    for (int k0 = 0; k0 < K_; k0 += KC) {
        // --- stage Y chunk, transposing (si, s) -> [s][si] ---
        {
            const float4* ysrc = (const float4*)(y + (size_t)(n * K_ + k0) * S_);
            #pragma unroll
            for (int it = 0; it < (KC * S_ / 4) / 256; ++it) {   // 8 iters
                int i  = t + it * 256;          // float4 index
                float4 v = ysrc[i];
                int f0 = i * 4;
                int kk  = f0 >> 8;
                int rem = f0 & 255;
                int si  = rem >> 6;
                int s0  = rem & 63;             // s0..s0+3, same si
                Ys[kk][s0 + 0][si] = v.x;
                Ys[kk][s0 + 1][si] = v.y;
                Ys[kk][s0 + 2][si] = v.z;
                Ys[kk][s0 + 3][si] = v.w;
            }
        }
        // --- stage W tiles: PG p-rows of 16 floats per kk ---
        {
            #pragma unroll
            for (int it = 0; it < (KC * PG * QR_ / 4) / 256; ++it) { // 4 iters
                int i   = t + it * 256;         // float4 index into [KC][PG][16]
                int kk  = i >> 5;
                int rem = i & 31;
                int p   = rem >> 2;
                int j4  = rem & 3;
                ((float4*)&Ws[kk][p][0])[j4] =
                    ((const float4*)(W + (size_t)(k0 + kk) * (NP_ * QR_)
                                       + (size_t)(pg * PG + p) * QR_))[j4];
            }
        }
        __syncthreads();

        #pragma unroll 2
        for (int kk = 0; kk < KC; ++kk) {
            // one vector load -> 4 spatial y values
            float4 yv = *(const float4*)&Ys[kk][s][0];
            unsigned long long yy[ST];
            yy[0] = pack2(yv.x, yv.x);
            yy[1] = pack2(yv.y, yv.y);
            yy[2] = pack2(yv.z, yv.z);
            yy[3] = pack2(yv.w, yv.w);

            #pragma unroll
            for (int pp = 0; pp < PT; ++pp) {
                const ulonglong2* wr = (const ulonglong2*)&Ws[kk][g * PT + pp][0];
                ulonglong2 w01 = wr[0];
                ulonglong2 w23 = wr[1];
                ulonglong2 w45 = wr[2];
                ulonglong2 w67 = wr[3];
                #pragma unroll
                for (int si = 0; si < ST; ++si) {
                    ffma2(acc[si][pp][0], yy[si], w01.x);
                    ffma2(acc[si][pp][1], yy[si], w01.y);
                    ffma2(acc[si][pp][2], yy[si], w23.x);
                    ffma2(acc[si][pp][3], yy[si], w23.y);
                    ffma2(acc[si][pp][4], yy[si], w45.x);
                    ffma2(acc[si][pp][5], yy[si], w45.y);
                    ffma2(acc[si][pp][6], yy[si], w67.x);
                    ffma2(acc[si][pp][7], yy[si], w67.y);
                }
            }
        }
        __syncthreads();
    }

    // --- write out ---
    #pragma unroll
    for (int si = 0; si < ST; ++si) {
        int s2 = si * 64 + s;
        int y_ = s2 >> 4;
        int z  = s2 & 15;
        #pragma unroll
        for (int pp = 0; pp < PT; ++pp) {
            float* ob = out + (size_t)n * 4194304
                            + (size_t)(pg * PG + g * PT + pp) * 4096
                            + y_ * 256 + z * 4;
            #pragma unroll
            for (int q = 0; q < 4; ++q) {
                float4 v;
                unpack2(acc[si][pp][2 * q],     v.x, v.y);
                unpack2(acc[si][pp][2 * q + 1], v.z, v.w);
                *(float4*)(ob + q * 64) = v;
            }
        }
    }
}

extern "C" void kernel_launch(void* const* d_in, const int* in_sizes, int n_in,
                              void* d_out, int out_size) {
    const float* y = (const float*)d_in[0];
    const float* W = (const float*)d_in[1];
    float* out = (float*)d_out;
    dim3 grid(B_, NP_ / PG);    // (8, 128) = 1024 blocks
    backproj_kernel<<<grid, 256>>>(y, W, out);
}

// round 4
// speedup vs baseline: 3.2201x; 2.5103x over previous
#include <cuda_runtime.h>
#include <cuda_bf16.h>
#include <cstdint>

// ---------------- problem constants ----------------
#define B_    8
#define K_    128
#define S_    256
#define NOUT  16384
#define M_    2048
#define KEFF  384            // 3 bf16-split passes x K=128
#define BM    128
#define BN    128
#define BK    32
#define NSTAGE 3
#define STAGE_BYTES (BM * 64 + BN * 64)   // 8KB A + 8KB B per stage
#define SM_TOTAL (NSTAGE * STAGE_BYTES)   // 49152

// ---------------- scratch: bf16 split, K-major, K_eff=384 ----------------
// A slots per k: [k]=hi, [128+k]=lo, [256+k]=hi
// B slots per k: [k]=hi, [128+k]=hi, [256+k]=lo
__device__ __nv_bfloat16 g_A[M_ * KEFF];
__device__ __nv_bfloat16 g_B[NOUT * KEFF];

// ---------------- helpers ----------------
__device__ __forceinline__ uint32_t smem_u32(const void* p) {
    uint32_t a;
    asm("{ .reg .u64 t; cvta.to.shared.u64 t, %1; cvt.u32.u64 %0, t; }" : "=r"(a) : "l"(p));
    return a;
}
__device__ __forceinline__ void cp_async16(uint32_t saddr, const void* gaddr) {
    asm volatile("cp.async.cg.shared.global [%0], [%1], 16;" :: "r"(saddr), "l"(gaddr));
}
__device__ __forceinline__ void cp_commit() {
    asm volatile("cp.async.commit_group;" ::: "memory");
}
__device__ __forceinline__ void cp_wait1() {
    asm volatile("cp.async.wait_group 1;" ::: "memory");
}
__device__ __forceinline__ void ldsm4(uint32_t& r0, uint32_t& r1, uint32_t& r2, uint32_t& r3,
                                      uint32_t addr) {
    asm volatile("ldmatrix.sync.aligned.m8n8.x4.shared.b16 {%0,%1,%2,%3}, [%4];"
                 : "=r"(r0), "=r"(r1), "=r"(r2), "=r"(r3) : "r"(addr));
}
__device__ __forceinline__ void mma16816(float* d, uint32_t a0, uint32_t a1, uint32_t a2,
                                         uint32_t a3, uint32_t b0, uint32_t b1) {
    asm volatile(
        "mma.sync.aligned.m16n8k16.row.col.f32.bf16.bf16.f32 "
        "{%0,%1,%2,%3}, {%4,%5,%6,%7}, {%8,%9}, {%0,%1,%2,%3};"
        : "+f"(d[0]), "+f"(d[1]), "+f"(d[2]), "+f"(d[3])
        : "r"(a0), "r"(a1), "r"(a2), "r"(a3), "r"(b0), "r"(b1));
}

// smem chunk swizzle: 64B rows of 4x16B chunks; conflict-free for 8-row ldmatrix phases
#define SWZ(row, c) ((c) ^ (((row) >> 1) & 3))

// ---------------- pre-kernel: fp32 [z][K][NC] -> bf16 split [z*NC + c][KEFF] ----------------
__global__ void split_transpose_bf16(const float* __restrict__ src, int NC, int isB) {
    __shared__ float tile[32][33];
    const int c0 = blockIdx.x * 32;
    const int k0 = blockIdx.y * 32;
    const int tx = threadIdx.x;   // 0..31
    const int ty = threadIdx.y;   // 0..7
    const size_t sb = (size_t)blockIdx.z * K_ * NC;
    const size_t db = (size_t)blockIdx.z * (size_t)NC * KEFF;
    __nv_bfloat16* dst = isB ? g_B : g_A;

    #pragma unroll
    for (int r = 0; r < 4; ++r)
        tile[ty + 8 * r][tx] = src[sb + (size_t)(k0 + ty + 8 * r) * NC + c0 + tx];
    __syncthreads();
    #pragma unroll
    for (int r = 0; r < 4; ++r) {
        int cc = c0 + ty + 8 * r;
        float a = tile[tx][ty + 8 * r];
        __nv_bfloat16 h = __float2bfloat16(a);
        __nv_bfloat16 l = __float2bfloat16(a - __bfloat162float(h));
        __nv_bfloat16* d = dst + db + (size_t)cc * KEFF + k0 + tx;
        if (isB) { d[0] = h; d[128] = h; d[256] = l; }
        else     { d[0] = h; d[128] = l; d[256] = h; }
    }
}

// ---------------- main GEMM kernel ----------------
__global__ __launch_bounds__(256, 2)
void gemm_bf16_kernel(float* __restrict__ out) {
    extern __shared__ char smem[];
    const uint32_t sbase = smem_u32(smem);
    const int tid  = threadIdx.x;
    const int lane = tid & 31;
    const int w    = tid >> 5;
    const int wm   = w >> 2;      // 0..1
    const int wn   = w & 3;       // 0..3
    const int bx   = blockIdx.x;  // n tile 0..127
    const int by   = blockIdx.y;  // m tile 0..15

    const __nv_bfloat16* gA = g_A + (size_t)by * BM * KEFF;
    const __nv_bfloat16* gB = g_B + (size_t)bx * BN * KEFF;

    float acc[4][4][4];
    #pragma unroll
    for (int i = 0; i < 4; ++i)
        #pragma unroll
        for (int j = 0; j < 4; ++j)
            #pragma unroll
            for (int k = 0; k < 4; ++k)
                acc[i][j][k] = 0.0f;

    // ---- async stage loader ----
    auto issue = [&](int kb, int s) {
        const int kk0 = kb * BK;
        const uint32_t st = sbase + s * STAGE_BYTES;
        #pragma unroll
        for (int it = 0; it < 2; ++it) {
            int ch  = tid + it * 256;     // 0..511
            int row = ch >> 2;
            int c   = ch & 3;
            uint32_t off = row * 64 + (SWZ(row, c) << 4);
            cp_async16(st + off, gA + (size_t)row * KEFF + kk0 + c * 8);
            cp_async16(st + BM * 64 + off, gB + (size_t)row * KEFF + kk0 + c * 8);
        }
    };

    issue(0, 0); cp_commit();
    issue(1, 1); cp_commit();

    const int NKB = KEFF / BK;   // 12
    for (int kb = 0; kb < NKB; ++kb) {
        const int s = kb % NSTAGE;
        cp_wait1();
        __syncthreads();
        if (kb + 2 < NKB) issue(kb + 2, (kb + 2) % NSTAGE);
        cp_commit();

        const uint32_t Ab = sbase + s * STAGE_BYTES;
        const uint32_t Bb = Ab + BM * 64;
        #pragma unroll
        for (int k16 = 0; k16 < 2; ++k16) {
            uint32_t br[4][2];
            #pragma unroll
            for (int ng = 0; ng < 2; ++ng) {
                int rown = wn * 32 + ng * 16 + ((lane >> 4) << 3) + (lane & 7);
                int cg   = k16 * 2 + ((lane >> 3) & 1);
                uint32_t addr = Bb + rown * 64 + (SWZ(rown, cg) << 4);
                uint32_t b0, b1, b2, b3;
                ldsm4(b0, b1, b2, b3, addr);
                br[ng * 2][0] = b0;     br[ng * 2][1] = b1;
                br[ng * 2 + 1][0] = b2; br[ng * 2 + 1][1] = b3;
            }
            #pragma unroll
            for (int mt = 0; mt < 4; ++mt) {
                int rowm = wm * 64 + mt * 16 + (lane & 15);
                int cg   = k16 * 2 + (lane >> 4);
                uint32_t addr = Ab + rowm * 64 + (SWZ(rowm, cg) << 4);
                uint32_t a0, a1, a2, a3;
                ldsm4(a0, a1, a2, a3, addr);
                #pragma unroll
                for (int nt = 0; nt < 4; ++nt)
                    mma16816(acc[mt][nt], a0, a1, a2, a3, br[nt][0], br[nt][1]);
            }
        }
    }
    __syncthreads();

    // ---- epilogue: 4 chunks of 32 m-rows via smem, warp-coherent stores ----
    float* ebuf = (float*)smem;               // [32][132] fp32 = 16896 B
    const int nn = by >> 1;                   // batch n
    for (int c = 0; c < 4; ++c) {
        if (wm == (c >> 1)) {
            #pragma unroll
            for (int t = 0; t < 2; ++t) {
                int mt = (c & 1) * 2 + t;
                int r0 = t * 16 + (lane >> 2);
                #pragma unroll
                for (int nt = 0; nt < 4; ++nt) {
                    int col = wn * 32 + nt * 8 + ((lane & 3) << 1);
                    *(float2*)&ebuf[r0 * 132 + col] =
                        make_float2(acc[mt][nt][0], acc[mt][nt][1]);
                    *(float2*)&ebuf[(r0 + 8) * 132 + col] =
                        make_float2(acc[mt][nt][2], acc[mt][nt][3]);
                }
            }
        }
        __syncthreads();
        #pragma unroll
        for (int k = 0; k < 4; ++k) {
            int j4 = w + 8 * k;               // 0..31: output j-quad
            int sg = (by & 1) * 128 + c * 32 + lane;
            int yy = sg >> 4, zz = sg & 15;
            float4 v = *(float4*)&ebuf[lane * 132 + j4 * 4];
            size_t addr = (size_t)nn * 4194304
                        + (size_t)(bx * 8 + (j4 >> 2)) * 4096
                        + yy * 256 + (j4 & 3) * 64 + zz * 4;
            *(float4*)(out + addr) = v;
        }
        __syncthreads();
    }
}

// ---------------- launch ----------------
extern "C" void kernel_launch(void* const* d_in, const int* in_sizes, int n_in,
                              void* d_out, int out_size) {
    const float* y = (const float*)d_in[0];   // [8][128][256]
    const float* W = (const float*)d_in[1];   // [128][16384]
    float* out = (float*)d_out;

    // split+transpose y -> g_A   (per n: [128][256] -> [256][384])
    split_transpose_bf16<<<dim3(S_ / 32, K_ / 32, B_), dim3(32, 8)>>>(y, S_, 0);
    // split+transpose W -> g_B   ([128][16384] -> [16384][384])
    split_transpose_bf16<<<dim3(NOUT / 32, K_ / 32, 1), dim3(32, 8)>>>(W, NOUT, 1);

    cudaFuncSetAttribute(gemm_bf16_kernel,
                         cudaFuncAttributeMaxDynamicSharedMemorySize, SM_TOTAL);
    dim3 grid(NOUT / BN, M_ / BM);   // (128, 16)
    gemm_bf16_kernel<<<grid, 256, SM_TOTAL>>>(out);
}

// round 5
// speedup vs baseline: 5.3413x; 1.6587x over previous
#include <cuda_runtime.h>
#include <cuda_fp16.h>
#include <cstdint>

// ---------------- problem constants ----------------
#define B_    8
#define K_    128
#define S_    256
#define NOUT  16384
#define M_    2048
#define BM    128
#define BN    128
#define BK    32
#define NKB   4                 // K_/BK
#define NSTAGE 3
#define STAGE_BYTES (BM * 64 + BN * 64)   // 8KB A + 8KB B per stage (BK=32 halves = 64B/row)
#define SM_TOTAL (NSTAGE * STAGE_BYTES)   // 49152

// ---------------- scratch: fp16, K-major ----------------
__device__ __half g_A[M_ * K_];      // 512 KB
__device__ __half g_B[NOUT * K_];    //   4 MB

// ---------------- helpers ----------------
__device__ __forceinline__ uint32_t smem_u32(const void* p) {
    uint32_t a;
    asm("{ .reg .u64 t; cvta.to.shared.u64 t, %1; cvt.u32.u64 %0, t; }" : "=r"(a) : "l"(p));
    return a;
}
__device__ __forceinline__ void cp_async16(uint32_t saddr, const void* gaddr) {
    asm volatile("cp.async.cg.shared.global [%0], [%1], 16;" :: "r"(saddr), "l"(gaddr));
}
__device__ __forceinline__ void cp_commit() {
    asm volatile("cp.async.commit_group;" ::: "memory");
}
__device__ __forceinline__ void cp_wait1() {
    asm volatile("cp.async.wait_group 1;" ::: "memory");
}
__device__ __forceinline__ void ldsm4(uint32_t& r0, uint32_t& r1, uint32_t& r2, uint32_t& r3,
                                      uint32_t addr) {
    asm volatile("ldmatrix.sync.aligned.m8n8.x4.shared.b16 {%0,%1,%2,%3}, [%4];"
                 : "=r"(r0), "=r"(r1), "=r"(r2), "=r"(r3) : "r"(addr));
}
__device__ __forceinline__ void mma16816(float* d, uint32_t a0, uint32_t a1, uint32_t a2,
                                         uint32_t a3, uint32_t b0, uint32_t b1) {
    asm volatile(
        "mma.sync.aligned.m16n8k16.row.col.f32.f16.f16.f32 "
        "{%0,%1,%2,%3}, {%4,%5,%6,%7}, {%8,%9}, {%0,%1,%2,%3};"
        : "+f"(d[0]), "+f"(d[1]), "+f"(d[2]), "+f"(d[3])
        : "r"(a0), "r"(a1), "r"(a2), "r"(a3), "r"(b0), "r"(b1));
}

// smem chunk swizzle: 64B rows of 4x16B chunks; conflict-free for 8-row ldmatrix phases
#define SWZ(row, c) ((c) ^ (((row) >> 1) & 3))

// ---------------- fused pre-kernel: fp32 [K][NC] -> fp16 [NC][K] transposed ----------------
// blocks 0..2047: W (NC=16384); blocks 2048..2303: y (8 batches, NC=256)
__global__ __launch_bounds__(256)
void convert_kernel(const float* __restrict__ y, const float* __restrict__ W) {
    __shared__ float tile[32][33];
    const int bid = blockIdx.x;
    const float* src;
    __half* dst;
    int NC, c_t, k_t;
    if (bid < 2048) {
        c_t = bid >> 2; k_t = bid & 3;
        src = W; dst = g_B; NC = NOUT;
    } else {
        int yb = bid - 2048;
        int z  = yb >> 5;
        c_t = (yb >> 2) & 7; k_t = yb & 3;
        src = y + (size_t)z * K_ * S_;
        dst = g_A + (size_t)z * S_ * K_;
        NC = S_;
    }
    const int tx = threadIdx.x & 31;
    const int ty = threadIdx.x >> 5;
    const int c0 = c_t * 32, k0 = k_t * 32;

    #pragma unroll
    for (int r = 0; r < 4; ++r)
        tile[ty + 8 * r][tx] = src[(size_t)(k0 + ty + 8 * r) * NC + c0 + tx];
    __syncthreads();
    #pragma unroll
    for (int r = 0; r < 4; ++r) {
        int cc = c0 + ty + 8 * r;
        dst[(size_t)cc * K_ + k0 + tx] = __float2half(tile[tx][ty + 8 * r]);
    }
}

// ---------------- main GEMM kernel ----------------
__global__ __launch_bounds__(256, 2)
void gemm_fp16_kernel(float* __restrict__ out) {
    extern __shared__ char smem[];
    const uint32_t sbase = smem_u32(smem);
    const int tid  = threadIdx.x;
    const int lane = tid & 31;
    const int w    = tid >> 5;
    const int wm   = w >> 2;      // 0..1
    const int wn   = w & 3;       // 0..3
    const int bx   = blockIdx.x;  // n tile 0..127
    const int by   = blockIdx.y;  // m tile 0..15

    const __half* gA = g_A + (size_t)by * BM * K_;
    const __half* gB = g_B + (size_t)bx * BN * K_;

    float acc[4][4][4];
    #pragma unroll
    for (int i = 0; i < 4; ++i)
        #pragma unroll
        for (int j = 0; j < 4; ++j)
            #pragma unroll
            for (int k = 0; k < 4; ++k)
                acc[i][j][k] = 0.0f;

    auto issue = [&](int kb, int s) {
        const int kk0 = kb * BK;
        const uint32_t st = sbase + s * STAGE_BYTES;
        #pragma unroll
        for (int it = 0; it < 2; ++it) {
            int ch  = tid + it * 256;     // 0..511
            int row = ch >> 2;
            int c   = ch & 3;
            uint32_t off = row * 64 + (SWZ(row, c) << 4);
            cp_async16(st + off, gA + (size_t)row * K_ + kk0 + c * 8);
            cp_async16(st + BM * 64 + off, gB + (size_t)row * K_ + kk0 + c * 8);
        }
    };

    issue(0, 0); cp_commit();
    issue(1, 1); cp_commit();

    for (int kb = 0; kb < NKB; ++kb) {
        const int s = kb % NSTAGE;
        cp_wait1();
        __syncthreads();
        if (kb + 2 < NKB) issue(kb + 2, (kb + 2) % NSTAGE);
        cp_commit();

        const uint32_t Ab = sbase + s * STAGE_BYTES;
        const uint32_t Bb = Ab + BM * 64;
        #pragma unroll
        for (int k16 = 0; k16 < 2; ++k16) {
            uint32_t br[4][2];
            #pragma unroll
            for (int ng = 0; ng < 2; ++ng) {
                int rown = wn * 32 + ng * 16 + ((lane >> 4) << 3) + (lane & 7);
                int cg   = k16 * 2 + ((lane >> 3) & 1);
                uint32_t addr = Bb + rown * 64 + (SWZ(rown, cg) << 4);
                uint32_t b0, b1, b2, b3;
                ldsm4(b0, b1, b2, b3, addr);
                br[ng * 2][0] = b0;     br[ng * 2][1] = b1;
                br[ng * 2 + 1][0] = b2; br[ng * 2 + 1][1] = b3;
            }
            #pragma unroll
            for (int mt = 0; mt < 4; ++mt) {
                int rowm = wm * 64 + mt * 16 + (lane & 15);
                int cg   = k16 * 2 + (lane >> 4);
                uint32_t addr = Ab + rowm * 64 + (SWZ(rowm, cg) << 4);
                uint32_t a0, a1, a2, a3;
                ldsm4(a0, a1, a2, a3, addr);
                #pragma unroll
                for (int nt = 0; nt < 4; ++nt)
                    mma16816(acc[mt][nt], a0, a1, a2, a3, br[nt][0], br[nt][1]);
            }
        }
    }
    __syncthreads();

    // ---- epilogue: 2 rounds of 64 m-rows via smem, warp-coherent float4 stores ----
    float* ebuf = (float*)smem;               // [64][132] fp32 = 33792 B < 48KB
    const int nn = by >> 1;
    #pragma unroll
    for (int c = 0; c < 2; ++c) {
        if (wm == c) {
            #pragma unroll
            for (int mt = 0; mt < 4; ++mt) {
                int r0 = mt * 16 + (lane >> 2);
                #pragma unroll
                for (int nt = 0; nt < 4; ++nt) {
                    int col = wn * 32 + nt * 8 + ((lane & 3) << 1);
                    *(float2*)&ebuf[r0 * 132 + col] =
                        make_float2(acc[mt][nt][0], acc[mt][nt][1]);
                    *(float2*)&ebuf[(r0 + 8) * 132 + col] =
                        make_float2(acc[mt][nt][2], acc[mt][nt][3]);
                }
            }
        }
        __syncthreads();
        #pragma unroll
        for (int k = 0; k < 8; ++k) {
            int j4 = w + 8 * (k >> 1);        // 0..31: output j-quad
            int r  = (k & 1) * 32 + lane;     // 0..63 within round
            int sg = (by & 1) * 128 + c * 64 + r;
            int yy = sg >> 4, zz = sg & 15;
            float4 v = *(float4*)&ebuf[r * 132 + j4 * 4];
            size_t addr = (size_t)nn * 4194304
                        + (size_t)(bx * 8 + (j4 >> 2)) * 4096
                        + yy * 256 + (j4 & 3) * 64 + zz * 4;
            *(float4*)(out + addr) = v;
        }
        __syncthreads();
    }
}

// ---------------- launch ----------------
extern "C" void kernel_launch(void* const* d_in, const int* in_sizes, int n_in,
                              void* d_out, int out_size) {
    const float* y = (const float*)d_in[0];   // [8][128][256]
    const float* W = (const float*)d_in[1];   // [128][16384]
    float* out = (float*)d_out;

    convert_kernel<<<2304, 256>>>(y, W);

    cudaFuncSetAttribute(gemm_fp16_kernel,
                         cudaFuncAttributeMaxDynamicSharedMemorySize, SM_TOTAL);
    dim3 grid(NOUT / BN, M_ / BM);   // (128, 16)
    gemm_fp16_kernel<<<grid, 256, SM_TOTAL>>>(out);
}